// round 14
// baseline (speedup 1.0000x reference)
#include <cuda_runtime.h>
#include <cuda_fp16.h>
#include <cstdint>
#include <cstddef>

// ================= problem constants =================
#define MAX_E 16000
#define MAX_N 2000

// ================= helpers =================
__device__ __forceinline__ uint32_t smem_to_u32(const void* smem_ptr) {
    uint32_t addr;
    asm("{ .reg .u64 tmp; cvta.to.shared.u64 tmp, %1; cvt.u32.u64 %0, tmp; }"
        : "=r"(addr) : "l"(smem_ptr));
    return addr;
}
#define SMEM_SWIZZLE_128B(byte_offset) ((byte_offset) ^ (((byte_offset) >> 3) & 0x70))

__device__ __forceinline__ void cp_async16(uint32_t dst, const void* src, bool valid) {
    int sz = valid ? 16 : 0;
    asm volatile("cp.async.cg.shared.global [%0], [%1], 16, %2;"
                 :: "r"(dst), "l"(src), "r"(sz) : "memory");
}
__device__ __forceinline__ void cp_commit() {
    asm volatile("cp.async.commit_group;" ::: "memory");
}
template <int N>
__device__ __forceinline__ void cp_wait() {
    asm volatile("cp.async.wait_group %0;" :: "n"(N) : "memory");
}
__device__ __forceinline__ void ldsm4(uint32_t& r0, uint32_t& r1, uint32_t& r2, uint32_t& r3,
                                      uint32_t addr) {
    asm volatile("ldmatrix.sync.aligned.m8n8.x4.shared.b16 {%0,%1,%2,%3}, [%4];"
                 : "=r"(r0), "=r"(r1), "=r"(r2), "=r"(r3) : "r"(addr));
}
__device__ __forceinline__ void mma16816(float* c, const uint32_t* a, uint32_t b0, uint32_t b1) {
    asm volatile(
        "mma.sync.aligned.m16n8k16.row.col.f32.f16.f16.f32 "
        "{%0,%1,%2,%3}, {%4,%5,%6,%7}, {%8,%9}, {%0,%1,%2,%3};"
        : "+f"(c[0]), "+f"(c[1]), "+f"(c[2]), "+f"(c[3])
        : "r"(a[0]), "r"(a[1]), "r"(a[2]), "r"(a[3]), "r"(b0), "r"(b1));
}

// ================= scratch =================
__device__ __align__(256) __half g_ein[(size_t)MAX_E * 768];
__device__ __align__(256) __half g_h1b[(size_t)MAX_E * 256];
__device__ __align__(256) __half g_eoutb[(size_t)MAX_E * 256];
__device__ __align__(256) __half g_xb[(size_t)MAX_N * 256];
__device__ __align__(256) __half g_qh[(size_t)MAX_N * 256];
__device__ __align__(256) __half g_kvh[(size_t)MAX_E * 512];
__device__ __align__(256) __half g_gattb[(size_t)MAX_N * 256];
__device__ __align__(256) __half g_cat[(size_t)MAX_N * 512];
__device__ __align__(256) __half g_h2b[(size_t)MAX_N * 256];
__device__ __align__(256) float  g_bkv[512];
__device__ __align__(256) float  g_vsum[256];
// CSR adjacency
__device__ int g_deg[MAX_N];
__device__ int g_off[MAX_N + 1];
__device__ int g_cursor[MAX_N];
__device__ int g_elist[MAX_E];
// single-term fp16 transposed weights [Ncols, K]
__device__ __align__(256) __half g_We1t[256 * 768];
__device__ __align__(256) __half g_We2t[256 * 256];
__device__ __align__(256) __half g_Wqt[256 * 256];
__device__ __align__(256) __half g_Wkvt[512 * 256];
__device__ __align__(256) __half g_Wot[256 * 256];
__device__ __align__(256) __half g_Wn1t[256 * 512];
__device__ __align__(256) __half g_Wn2t[256 * 256];

// ================= prep (weights + xprep + zero deg/vsum + bkv) =================
struct WPA {
    const float* W[8];
    __half* O[8];
    int K[8];
    int start[9];
};
__global__ void prep_all_kernel(WPA a, int wblocks,
                                const float* __restrict__ x, __half* __restrict__ xb,
                                const float* __restrict__ bk, const float* __restrict__ bv,
                                float* __restrict__ bkv, float* __restrict__ vsum,
                                int* __restrict__ deg, int M) {
    if (blockIdx.x < wblocks) {
        int b = blockIdx.x;
        int i = 0;
        #pragma unroll
        for (int j = 1; j < 8; j++) if (b >= a.start[j]) i = j;
        int k = b - a.start[i];
        int K = a.K[i];
        int col = threadIdx.x;
        a.O[i][(size_t)col * K + k] = __float2half_rn(a.W[i][(size_t)k * 256 + col]);
        return;
    }
    int idx = (blockIdx.x - wblocks) * blockDim.x + threadIdx.x;
    if (idx < M * 256)
        xb[idx] = __float2half_rn(x[idx]);
    int r = idx - M * 256;
    if (r >= 0 && r < M) deg[r] = 0;
    int v = idx - M * 256 - M;
    if (v >= 0 && v < 256) vsum[v] = 0.f;
    int bidx = idx - M * 256 - M - 256;
    if (bidx >= 0 && bidx < 512)
        bkv[bidx] = (bidx < 256) ? bk[bidx] : bv[bidx - 256];
}

// GN(768, 32 groups of 24)+ReLU over concat(x[row],x[col],ea) -> fp16 [E,768]; counts deg.
__global__ void gn_edge_kernel(const float* __restrict__ x, const int* __restrict__ ei,
                               const float* __restrict__ ea,
                               const float* __restrict__ gamma, const float* __restrict__ beta,
                               __half* __restrict__ out, int* __restrict__ deg, int E) {
    __shared__ float buf[768];
    __shared__ float s_mu[32], s_rs[32];
    int e = blockIdx.x;
    int t = threadIdx.x;
    int r = ei[e];
    int c = ei[E + e];
    if (t == 0) atomicAdd(&deg[c], 1);
    buf[t]       = x[(size_t)r * 256 + t];
    buf[256 + t] = x[(size_t)c * 256 + t];
    buf[512 + t] = ea[(size_t)e * 256 + t];
    __syncthreads();
    if (t < 32) {
        float s = 0.f, s2 = 0.f;
        #pragma unroll
        for (int i = 0; i < 24; i++) { float v = buf[t * 24 + i]; s += v; s2 += v * v; }
        float m = s * (1.f / 24.f);
        float var = s2 * (1.f / 24.f) - m * m;
        s_mu[t] = m; s_rs[t] = rsqrtf(var + 1e-5f);
    }
    __syncthreads();
    size_t base = (size_t)e * 768;
    #pragma unroll
    for (int i = t; i < 768; i += 256) {
        int grp = i / 24;
        float v = fmaxf((buf[i] - s_mu[grp]) * s_rs[grp] * gamma[i] + beta[i], 0.f);
        out[base + i] = __float2half_rn(v);
    }
}

// exclusive prefix over deg -> off, cursor (single block, 256 threads)
__global__ void prefix_kernel(const int* __restrict__ deg, int* __restrict__ off,
                              int* __restrict__ cursor, int N) {
    __shared__ int buf[256];
    __shared__ int s_carry;
    int t = threadIdx.x;
    if (t == 0) s_carry = 0;
    __syncthreads();
    for (int base = 0; base < N; base += 256) {
        int carry = s_carry;
        int i = base + t;
        int v = (i < N) ? deg[i] : 0;
        buf[t] = v;
        __syncthreads();
        #pragma unroll
        for (int ofs = 1; ofs < 256; ofs <<= 1) {
            int add = (t >= ofs) ? buf[t - ofs] : 0;
            __syncthreads();
            buf[t] += add;
            __syncthreads();
        }
        int exc = buf[t] - v + carry;
        if (i < N) { off[i] = exc; cursor[i] = exc; }
        __syncthreads();
        if (t == 0) s_carry = carry + buf[255];
        __syncthreads();
    }
    if (t == 0) off[N] = s_carry;
}

__global__ void fill_kernel(const int* __restrict__ ei, int* __restrict__ cursor,
                            int* __restrict__ elist, int E) {
    int e = blockIdx.x * blockDim.x + threadIdx.x;
    if (e < E) {
        int n = ei[E + e];
        int pos = atomicAdd(&cursor[n], 1);
        elist[pos] = e;
    }
}

__global__ void colsum_kernel(const __half* __restrict__ kv, float* __restrict__ vsum, int E) {
    int t = threadIdx.x;
    float s = 0.f;
    for (int e = blockIdx.x; e < E; e += gridDim.x)
        s += __half2float(kv[(size_t)e * 512 + 256 + t]);
    atomicAdd(&vsum[t], s);
}

// per-node attention (CSR) + fused GN(x)->cat left half. Block = node, thread = channel.
__global__ void node_attn_kernel(const __half* __restrict__ q, const __half* __restrict__ kv,
                                 const int* __restrict__ elist, const int* __restrict__ off,
                                 const float* __restrict__ vsum, float invE,
                                 __half* __restrict__ gattb,
                                 const float* __restrict__ x,
                                 const float* __restrict__ gng, const float* __restrict__ gnb,
                                 __half* __restrict__ cat, int N) {
    __shared__ float wsum[8];
    __shared__ float wexp4[4];
    __shared__ float esumS[4];
    int n = blockIdx.x;
    int t = threadIdx.x;
    int h = t >> 6;
    int warp = t >> 5, lane = t & 31;

    float qv = __half2float(q[(size_t)n * 256 + t]);
    int o0 = off[n];
    int d = off[n + 1] - o0;
    float vacc = 0.f;
    float esum = 0.f;  // valid on t<4 (t == head)

    for (int j = 0; j < d; j++) {
        int e = elist[o0 + j];
        float kf = __half2float(kv[(size_t)e * 512 + t]);
        float vf = __half2float(kv[(size_t)e * 512 + 256 + t]);
        float p = qv * kf;
        #pragma unroll
        for (int ofs = 16; ofs >= 1; ofs >>= 1)
            p += __shfl_xor_sync(0xffffffffu, p, ofs);
        if (lane == 0) wsum[warp] = p;
        __syncthreads();
        if (t < 4) {
            float w = expf((wsum[2 * t] + wsum[2 * t + 1]) * 0.125f);
            wexp4[t] = w;
            esum += w;
        }
        __syncthreads();
        vacc += wexp4[h] * vf;
        // next iteration's wsum write is safe: it comes after another __syncthreads-free
        // region only touching registers, and wexp4 reads complete before the next
        // lane0 wsum store is observed (separated by the loop's first __syncthreads).
        __syncthreads();
    }
    if (t < 4) esumS[t] = esum;
    __syncthreads();
    float es = esumS[h];
    float val = (d > 0) ? vacc / es : vsum[t] * invE;
    gattb[(size_t)n * 256 + t] = __float2half_rn(val);

    // GN(x[n], groups of 8)+ReLU -> cat left half
    float xv = x[(size_t)n * 256 + t];
    float s = xv, s2 = xv * xv;
    #pragma unroll
    for (int ofs = 1; ofs <= 4; ofs <<= 1) {
        s  += __shfl_xor_sync(0xffffffffu, s, ofs);
        s2 += __shfl_xor_sync(0xffffffffu, s2, ofs);
    }
    float m = s * 0.125f;
    float var = s2 * 0.125f - m * m;
    float rs = rsqrtf(var + 1e-5f);
    float xo = fmaxf((xv - m) * rs * gng[t] + gnb[t], 0.f);
    cat[(size_t)n * 512 + t] = __float2half_rn(xo);
}

// ================= templated mma.sync GEMM =================
template <bool GN, bool MERGE>
__global__ void __launch_bounds__(256) tc_gemm_kernel(
    const __half* A1, int KC,
    const __half* B1,
    const float* bias,
    const float* __restrict__ resid,
    float* __restrict__ Cf, int ldc,
    __half* Cb, int bld, int bofs,
    const float* __restrict__ gng, const float* __restrict__ gnb,
    int M,
    const __half* Aq, const __half* Bq, const float* biasq, __half* Cbq, int Mq)
{
    int colBase = blockIdx.y * 256;
    if (MERGE && blockIdx.y == 2) {
        A1 = Aq; B1 = Bq; bias = biasq; Cb = Cbq; bld = 256; M = Mq; colBase = 0;
    }
    int rowBase = blockIdx.x * 128;
    if (rowBase >= M) return;

    extern __shared__ char smem_raw[];
    char* smem = (char*)(((uintptr_t)smem_raw + 1023) & ~(uintptr_t)1023);
    uint32_t sbase = smem_to_u32(smem);

    int tid = threadIdx.x;
    int wid = tid >> 5;
    int lane = tid & 31;
    int g = lane >> 2, tg = lane & 3;
    int wm = (wid >> 2) * 64;
    int wn = (wid & 3) * 64;

    int ar = tid >> 1;
    int au = (tid & 1) * 4;
    bool avalid = (rowBase + ar) < M;
    const char* Arow = (const char*)(A1 + (size_t)(rowBase + ar) * (KC * 64));
    const char* Brow = (const char*)(B1 + (size_t)(colBase + tid) * (KC * 64));

    auto load_chunk = [&](int c, int st) {
        uint32_t pA = sbase + st * 16384;
        uint32_t pB = sbase + 49152 + st * 32768;
        #pragma unroll
        for (int j = 0; j < 4; j++)
            cp_async16(pA + SMEM_SWIZZLE_128B(ar * 128 + (au + j) * 16),
                       Arow + (size_t)c * 128 + (au + j) * 16, avalid);
        #pragma unroll
        for (int j = 0; j < 8; j++)
            cp_async16(pB + SMEM_SWIZZLE_128B(tid * 128 + j * 16),
                       Brow + (size_t)c * 128 + j * 16, true);
    };

    float acc[4][8][4];
    #pragma unroll
    for (int mt = 0; mt < 4; mt++)
        #pragma unroll
        for (int nt = 0; nt < 8; nt++)
            #pragma unroll
            for (int i = 0; i < 4; i++) acc[mt][nt][i] = 0.f;

    load_chunk(0, 0); cp_commit();
    if (KC > 1) { load_chunk(1, 1); }
    cp_commit();

    uint32_t l15 = (uint32_t)(lane & 15);
    uint32_t lx  = (uint32_t)((lane & 7) << 4);
    uint32_t hi  = (uint32_t)(lane & 16);
    uint32_t aRowOff = (uint32_t)(wm + l15) * 128;
    uint32_t bRowOff = (uint32_t)(wn + l15) * 128;

    int st = 0;
    for (int c = 0; c < KC; c++) {
        cp_wait<1>();
        __syncthreads();
        if (c + 2 < KC) {
            int nst = st + 2; if (nst >= 3) nst -= 3;
            load_chunk(c + 2, nst);
        }
        cp_commit();

        uint32_t aB = sbase + st * 16384 + aRowOff;
        uint32_t bB = sbase + 49152 + st * 32768 + bRowOff;
        #pragma unroll
        for (int ks = 0; ks < 4; ks++) {
            uint32_t colp = ((uint32_t)(ks * 32) + hi) ^ lx;
            uint32_t a[4][4];
            #pragma unroll
            for (int mt = 0; mt < 4; mt++)
                ldsm4(a[mt][0], a[mt][1], a[mt][2], a[mt][3], aB + mt * 2048 + colp);
            #pragma unroll
            for (int ntp = 0; ntp < 4; ntp++) {
                uint32_t b0e, b0o, b1e, b1o;
                ldsm4(b0e, b0o, b1e, b1o, bB + ntp * 2048 + colp);
                #pragma unroll
                for (int mt = 0; mt < 4; mt++) {
                    mma16816(acc[mt][2 * ntp],     a[mt], b0e, b1e);
                    mma16816(acc[mt][2 * ntp + 1], a[mt], b0o, b1o);
                }
            }
        }
        st++; if (st >= 3) st = 0;
    }

    #pragma unroll
    for (int mt = 0; mt < 4; mt++) {
        #pragma unroll
        for (int half = 0; half < 2; half++) {
            int row = rowBase + wm + mt * 16 + g + half * 8;
            bool rv = row < M;
            #pragma unroll
            for (int nt = 0; nt < 8; nt++) {
                int col = wn + nt * 8 + tg * 2;
                int gcol = colBase + col;
                float v0 = acc[mt][nt][half * 2 + 0];
                float v1 = acc[mt][nt][half * 2 + 1];
                float2 bv = *(const float2*)(bias + gcol);
                v0 += bv.x; v1 += bv.y;
                if (resid && rv) {
                    float2 rvv = *(const float2*)(resid + (size_t)row * 256 + gcol);
                    v0 += rvv.x; v1 += rvv.y;
                }
                if (GN) {
                    float s = v0 + v1;
                    float s2 = v0 * v0 + v1 * v1;
                    s  += __shfl_xor_sync(0xffffffffu, s, 1);
                    s  += __shfl_xor_sync(0xffffffffu, s, 2);
                    s2 += __shfl_xor_sync(0xffffffffu, s2, 1);
                    s2 += __shfl_xor_sync(0xffffffffu, s2, 2);
                    float m = s * 0.125f;
                    float var = s2 * 0.125f - m * m;
                    float rs = rsqrtf(var + 1e-5f);
                    float2 gg = *(const float2*)(gng + gcol);
                    float2 bb = *(const float2*)(gnb + gcol);
                    v0 = fmaxf((v0 - m) * rs * gg.x + bb.x, 0.f);
                    v1 = fmaxf((v1 - m) * rs * gg.y + bb.y, 0.f);
                }
                if (rv) {
                    if (Cf)
                        *(float2*)(Cf + (size_t)row * ldc + gcol) = make_float2(v0, v1);
                    if (Cb) {
                        __half* o = Cb + (size_t)row * bld + bofs + gcol;
                        *(__half2*)(o) = __halves2half2(__float2half_rn(v0), __float2half_rn(v1));
                    }
                }
            }
        }
    }
}

// ================= launch =================
extern "C" void kernel_launch(void* const* d_in, const int* in_sizes, int n_in,
                              void* d_out, int out_size) {
    const float* x       = (const float*)d_in[0];
    const int*   ei      = (const int*)d_in[1];
    const float* ea      = (const float*)d_in[2];
    const float* gn_e1_g = (const float*)d_in[3];
    const float* gn_e1_b = (const float*)d_in[4];
    const float* We1     = (const float*)d_in[5];
    const float* be1     = (const float*)d_in[6];
    const float* gn_e2_g = (const float*)d_in[7];
    const float* gn_e2_b = (const float*)d_in[8];
    const float* We2     = (const float*)d_in[9];
    const float* be2     = (const float*)d_in[10];
    const float* gn_n_g  = (const float*)d_in[11];
    const float* gn_n_b  = (const float*)d_in[12];
    const float* Wq      = (const float*)d_in[13];
    const float* bq      = (const float*)d_in[14];
    const float* Wk      = (const float*)d_in[15];
    const float* bk      = (const float*)d_in[16];
    const float* Wv      = (const float*)d_in[17];
    const float* bv      = (const float*)d_in[18];
    const float* Wo      = (const float*)d_in[19];
    const float* bo      = (const float*)d_in[20];
    const float* Wn1     = (const float*)d_in[21];
    const float* bn1     = (const float*)d_in[22];
    const float* gn_n2_g = (const float*)d_in[23];
    const float* gn_n2_b = (const float*)d_in[24];
    const float* Wn2     = (const float*)d_in[25];
    const float* bn2     = (const float*)d_in[26];

    const int N = in_sizes[0] / 256;
    const int E = in_sizes[2] / 256;

    __half *ein, *h1b, *eoutb, *xb, *qh, *kvh, *gattb, *cat, *h2b;
    __half *We1t, *We2t, *Wqt, *Wkvt, *Wot, *Wn1t, *Wn2t;
    float *bkv, *vsum;
    int *deg, *off, *cursor, *elist;
    cudaGetSymbolAddress((void**)&ein,    g_ein);
    cudaGetSymbolAddress((void**)&h1b,    g_h1b);
    cudaGetSymbolAddress((void**)&eoutb,  g_eoutb);
    cudaGetSymbolAddress((void**)&xb,     g_xb);
    cudaGetSymbolAddress((void**)&qh,     g_qh);
    cudaGetSymbolAddress((void**)&kvh,    g_kvh);
    cudaGetSymbolAddress((void**)&gattb,  g_gattb);
    cudaGetSymbolAddress((void**)&cat,    g_cat);
    cudaGetSymbolAddress((void**)&h2b,    g_h2b);
    cudaGetSymbolAddress((void**)&bkv,    g_bkv);
    cudaGetSymbolAddress((void**)&vsum,   g_vsum);
    cudaGetSymbolAddress((void**)&deg,    g_deg);
    cudaGetSymbolAddress((void**)&off,    g_off);
    cudaGetSymbolAddress((void**)&cursor, g_cursor);
    cudaGetSymbolAddress((void**)&elist,  g_elist);
    cudaGetSymbolAddress((void**)&We1t,   g_We1t);
    cudaGetSymbolAddress((void**)&We2t,   g_We2t);
    cudaGetSymbolAddress((void**)&Wqt,    g_Wqt);
    cudaGetSymbolAddress((void**)&Wkvt,   g_Wkvt);
    cudaGetSymbolAddress((void**)&Wot,    g_Wot);
    cudaGetSymbolAddress((void**)&Wn1t,   g_Wn1t);
    cudaGetSymbolAddress((void**)&Wn2t,   g_Wn2t);

    float* n_out = (float*)d_out;
    float* e_out = (float*)d_out + (size_t)N * 256;

    const int DSMEM = 147456 + 1024;
    cudaFuncSetAttribute(tc_gemm_kernel<false, false>, cudaFuncAttributeMaxDynamicSharedMemorySize, DSMEM);
    cudaFuncSetAttribute(tc_gemm_kernel<true,  false>, cudaFuncAttributeMaxDynamicSharedMemorySize, DSMEM);
    cudaFuncSetAttribute(tc_gemm_kernel<false, true>,  cudaFuncAttributeMaxDynamicSharedMemorySize, DSMEM);

    int gemmE = (E + 127) / 128;
    int gemmN = (N + 127) / 128;

    WPA wpa;
    wpa.W[0] = We1; wpa.O[0] = We1t;           wpa.K[0] = 768;
    wpa.W[1] = We2; wpa.O[1] = We2t;           wpa.K[1] = 256;
    wpa.W[2] = Wq;  wpa.O[2] = Wqt;            wpa.K[2] = 256;
    wpa.W[3] = Wk;  wpa.O[3] = Wkvt;           wpa.K[3] = 256;
    wpa.W[4] = Wv;  wpa.O[4] = Wkvt + 256*256; wpa.K[4] = 256;
    wpa.W[5] = Wo;  wpa.O[5] = Wot;            wpa.K[5] = 256;
    wpa.W[6] = Wn1; wpa.O[6] = Wn1t;           wpa.K[6] = 512;
    wpa.W[7] = Wn2; wpa.O[7] = Wn2t;           wpa.K[7] = 256;
    int acc0 = 0;
    for (int i = 0; i < 8; i++) { wpa.start[i] = acc0; acc0 += wpa.K[i]; }
    wpa.start[8] = acc0;
    int miscTot = N * 256 + N + 256 + 512;
    int miscBlocks = (miscTot + 255) / 256;
    prep_all_kernel<<<acc0 + miscBlocks, 256>>>(wpa, acc0, x, xb, bk, bv, bkv, vsum, deg, N);

    // edge input GN + degree count
    gn_edge_kernel<<<E, 256>>>(x, ei, ea, gn_e1_g, gn_e1_b, ein, deg, E);
    // CSR build (can run while GEMMs execute; stream-ordered anyway)
    prefix_kernel<<<1, 256>>>(deg, off, cursor, N);
    fill_kernel<<<(E + 255) / 256, 256>>>(ei, cursor, elist, E);

    // h1b = GN(ein @ We1 + be1)+ReLU fused
    tc_gemm_kernel<true, false><<<dim3(gemmE, 1), 256, DSMEM>>>(
        ein, 12, We1t, be1, nullptr, nullptr, 0, h1b, 256, 0, gn_e2_g, gn_e2_b, E,
        nullptr, nullptr, nullptr, nullptr, 0);
    // e_out = h1b @ We2 + be2 + ea
    tc_gemm_kernel<false, false><<<dim3(gemmE, 1), 256, DSMEM>>>(
        h1b, 4, We2t, be2, ea, e_out, 256, eoutb, 256, 0, nullptr, nullptr, E,
        nullptr, nullptr, nullptr, nullptr, 0);
    // kv (2 col-halves) + q merged
    tc_gemm_kernel<false, true><<<dim3(gemmE, 3), 256, DSMEM>>>(
        eoutb, 4, Wkvt, bkv, nullptr, nullptr, 0, kvh, 512, 0, nullptr, nullptr, E,
        xb, Wqt, bq, qh, N);
    // attention
    colsum_kernel<<<64, 256>>>(kvh, vsum, E);
    node_attn_kernel<<<N, 256>>>(qh, kvh, elist, off, vsum, 1.0f / (float)E,
                                 gattb, x, gn_n_g, gn_n_b, cat, N);
    // g_o = gattb @ Wo + bo -> cat right half
    tc_gemm_kernel<false, false><<<dim3(gemmN, 1), 256, DSMEM>>>(
        gattb, 4, Wot, bo, nullptr, nullptr, 0, cat, 512, 256, nullptr, nullptr, N,
        nullptr, nullptr, nullptr, nullptr, 0);
    // h2b = GN(cat @ Wn1 + bn1)+ReLU fused
    tc_gemm_kernel<true, false><<<dim3(gemmN, 1), 256, DSMEM>>>(
        cat, 8, Wn1t, bn1, nullptr, nullptr, 0, h2b, 256, 0, gn_n2_g, gn_n2_b, N,
        nullptr, nullptr, nullptr, nullptr, 0);
    // n_out = h2b @ Wn2 + bn2 + x
    tc_gemm_kernel<false, false><<<dim3(gemmN, 1), 256, DSMEM>>>(
        h2b, 4, Wn2t, bn2, x, n_out, 256, nullptr, 0, 0, nullptr, nullptr, N,
        nullptr, nullptr, nullptr, nullptr, 0);
}

// round 15
// speedup vs baseline: 1.0575x; 1.0575x over previous
#include <cuda_runtime.h>
#include <cuda_fp16.h>
#include <cstdint>
#include <cstddef>

// ================= problem constants =================
#define MAX_E 16000
#define MAX_N 2000

// ================= helpers =================
__device__ __forceinline__ uint32_t smem_to_u32(const void* smem_ptr) {
    uint32_t addr;
    asm("{ .reg .u64 tmp; cvta.to.shared.u64 tmp, %1; cvt.u32.u64 %0, tmp; }"
        : "=r"(addr) : "l"(smem_ptr));
    return addr;
}
#define SMEM_SWIZZLE_128B(byte_offset) ((byte_offset) ^ (((byte_offset) >> 3) & 0x70))

__device__ __forceinline__ void cp_async16(uint32_t dst, const void* src, bool valid) {
    int sz = valid ? 16 : 0;
    asm volatile("cp.async.cg.shared.global [%0], [%1], 16, %2;"
                 :: "r"(dst), "l"(src), "r"(sz) : "memory");
}
__device__ __forceinline__ void cp_commit() {
    asm volatile("cp.async.commit_group;" ::: "memory");
}
template <int N>
__device__ __forceinline__ void cp_wait() {
    asm volatile("cp.async.wait_group %0;" :: "n"(N) : "memory");
}
__device__ __forceinline__ void ldsm4(uint32_t& r0, uint32_t& r1, uint32_t& r2, uint32_t& r3,
                                      uint32_t addr) {
    asm volatile("ldmatrix.sync.aligned.m8n8.x4.shared.b16 {%0,%1,%2,%3}, [%4];"
                 : "=r"(r0), "=r"(r1), "=r"(r2), "=r"(r3) : "r"(addr));
}
__device__ __forceinline__ void mma16816(float* c, const uint32_t* a, uint32_t b0, uint32_t b1) {
    asm volatile(
        "mma.sync.aligned.m16n8k16.row.col.f32.f16.f16.f32 "
        "{%0,%1,%2,%3}, {%4,%5,%6,%7}, {%8,%9}, {%0,%1,%2,%3};"
        : "+f"(c[0]), "+f"(c[1]), "+f"(c[2]), "+f"(c[3])
        : "r"(a[0]), "r"(a[1]), "r"(a[2]), "r"(a[3]), "r"(b0), "r"(b1));
}

// ================= scratch =================
__device__ __align__(256) __half g_ein[(size_t)MAX_E * 768];
__device__ __align__(256) __half g_h1b[(size_t)MAX_E * 256];
__device__ __align__(256) __half g_eoutb[(size_t)MAX_E * 256];
__device__ __align__(256) __half g_xb[(size_t)MAX_N * 256];
__device__ __align__(256) __half g_qh[(size_t)MAX_N * 256];
__device__ __align__(256) __half g_kvh[(size_t)MAX_E * 512];
__device__ __align__(256) float  g_attbuf[(size_t)MAX_N * 256 + MAX_N * 4 + 256];
__device__ __align__(256) __half g_gattb[(size_t)MAX_N * 256];
__device__ __align__(256) __half g_cat[(size_t)MAX_N * 512];
__device__ __align__(256) __half g_h2b[(size_t)MAX_N * 256];
__device__ __align__(256) float  g_bkv[512];
// single-term fp16 transposed weights [Ncols, K]
__device__ __align__(256) __half g_We1t[256 * 768];
__device__ __align__(256) __half g_We2t[256 * 256];
__device__ __align__(256) __half g_Wqt[256 * 256];
__device__ __align__(256) __half g_Wkvt[512 * 256];
__device__ __align__(256) __half g_Wot[256 * 256];
__device__ __align__(256) __half g_Wn1t[256 * 512];
__device__ __align__(256) __half g_Wn2t[256 * 256];

// ================= fused prep =================
struct WPA {
    const float* W[8];
    __half* O[8];
    int K[8];
    int start[9];
};
__global__ void wprep_all_kernel(WPA a) {
    int b = blockIdx.x;
    int i = 0;
    #pragma unroll
    for (int j = 1; j < 8; j++) if (b >= a.start[j]) i = j;
    int k = b - a.start[i];
    int K = a.K[i];
    int col = threadIdx.x;
    a.O[i][(size_t)col * K + k] = __float2half_rn(a.W[i][(size_t)k * 256 + col]);
}

__global__ void misc_prep_kernel(const float* __restrict__ x, __half* __restrict__ xb,
                                 float* __restrict__ attbuf, int zcount,
                                 const float* __restrict__ bk, const float* __restrict__ bv,
                                 float* __restrict__ bkv, int M) {
    int idx = blockIdx.x * blockDim.x + threadIdx.x;
    if (idx < M * 256)
        xb[idx] = __float2half_rn(x[idx]);
    int z = idx - M * 256;
    if (z >= 0 && z < zcount) attbuf[z] = 0.f;
    int bidx = idx - M * 256 - zcount;
    if (bidx >= 0 && bidx < 512)
        bkv[bidx] = (bidx < 256) ? bk[bidx] : bv[bidx - 256];
}

// GN(768, 32 groups of 24)+ReLU over concat(x[row],x[col],ea) -> fp16 [E,768]
__global__ void gn_edge_kernel(const float* __restrict__ x, const int* __restrict__ ei,
                               const float* __restrict__ ea,
                               const float* __restrict__ gamma, const float* __restrict__ beta,
                               __half* __restrict__ out, int E) {
    __shared__ float buf[768];
    __shared__ float s_mu[32], s_rs[32];
    int e = blockIdx.x;
    int t = threadIdx.x;
    int r = ei[e];
    int c = ei[E + e];
    buf[t]       = x[(size_t)r * 256 + t];
    buf[256 + t] = x[(size_t)c * 256 + t];
    buf[512 + t] = ea[(size_t)e * 256 + t];
    __syncthreads();
    if (t < 32) {
        float s = 0.f, s2 = 0.f;
        #pragma unroll
        for (int i = 0; i < 24; i++) { float v = buf[t * 24 + i]; s += v; s2 += v * v; }
        float m = s * (1.f / 24.f);
        float var = s2 * (1.f / 24.f) - m * m;
        s_mu[t] = m; s_rs[t] = rsqrtf(var + 1e-5f);
    }
    __syncthreads();
    size_t base = (size_t)e * 768;
    #pragma unroll
    for (int i = t; i < 768; i += 256) {
        int grp = i / 24;
        float v = fmaxf((buf[i] - s_mu[grp]) * s_rs[grp] * gamma[i] + beta[i], 0.f);
        out[base + i] = __float2half_rn(v);
    }
}

// GN(256, groups of 8)+ReLU over fp32 input -> fp16 out (x -> cat left half)
__global__ void gn256b_kernel(const float* __restrict__ in, const float* __restrict__ gamma,
                              const float* __restrict__ beta, __half* __restrict__ out,
                              int bld, int bofs, int M) {
    int t = threadIdx.x;
    int row = blockIdx.x * 8 + (t >> 5);
    if (row >= M) return;
    int g = t & 31;
    const float* p = in + (size_t)row * 256 + g * 8;
    float4 a = *(const float4*)p;
    float4 b = *(const float4*)(p + 4);
    float s = a.x + a.y + a.z + a.w + b.x + b.y + b.z + b.w;
    float s2 = a.x*a.x + a.y*a.y + a.z*a.z + a.w*a.w + b.x*b.x + b.y*b.y + b.z*b.z + b.w*b.w;
    float m = s * 0.125f;
    float var = s2 * 0.125f - m * m;
    float rs = rsqrtf(var + 1e-5f);
    float vals[8] = {a.x, a.y, a.z, a.w, b.x, b.y, b.z, b.w};
    __half hs[8];
    #pragma unroll
    for (int i = 0; i < 8; i++) {
        int ch = g * 8 + i;
        hs[i] = __float2half_rn(fmaxf((vals[i] - m) * rs * gamma[ch] + beta[ch], 0.f));
    }
    __half* o = out + (size_t)row * bld + bofs + g * 8;
    #pragma unroll
    for (int i = 0; i < 4; i++)
        *(__half2*)(o + 2*i) = __halves2half2(hs[2*i], hs[2*i+1]);
}

__global__ void colsum_kernel(const __half* __restrict__ kv, float* __restrict__ vsum, int E) {
    int t = threadIdx.x;
    float s = 0.f;
    for (int e = blockIdx.x; e < E; e += gridDim.x)
        s += __half2float(kv[(size_t)e * 512 + 256 + t]);
    atomicAdd(&vsum[t], s);
}

// 2 edges per block, 128 threads/edge, half2 math. warp = sub*4 + head.
__global__ void attn_scatter2_kernel(const __half* __restrict__ q, const __half* __restrict__ kv,
                                     const int* __restrict__ ei,
                                     float* __restrict__ expsum, float* __restrict__ gatt, int E) {
    __shared__ float wsum[8];
    __shared__ float wexp[2][4];
    int t = threadIdx.x;
    int sub = t >> 7;
    int tt = t & 127;
    int e = blockIdx.x * 2 + sub;
    bool ev = e < E;
    int n = 0;
    float p = 0.f;
    float2 vf = make_float2(0.f, 0.f);
    if (ev) {
        n = ei[E + e];
        __half2 qv = *(const __half2*)(q + (size_t)n * 256 + 2 * tt);
        __half2 kvv = *(const __half2*)(kv + (size_t)e * 512 + 2 * tt);
        __half2 vv = *(const __half2*)(kv + (size_t)e * 512 + 256 + 2 * tt);
        float2 qf = __half22float2(qv);
        float2 kf = __half22float2(kvv);
        vf = __half22float2(vv);
        p = qf.x * kf.x + qf.y * kf.y;
    }
    #pragma unroll
    for (int off = 16; off >= 1; off >>= 1)
        p += __shfl_xor_sync(0xffffffffu, p, off);
    int warp = t >> 5, lane = t & 31;
    if (lane == 0) wsum[warp] = p;
    __syncthreads();
    if (t < 8) {
        int s = t >> 2, h = t & 3;
        float w = expf(wsum[t] * 0.125f);
        wexp[s][h] = w;
        int ee = blockIdx.x * 2 + s;
        if (ee < E)
            atomicAdd(&expsum[ei[E + ee] * 4 + h], w);
    }
    __syncthreads();
    if (ev) {
        float w = wexp[sub][tt >> 5];
        atomicAdd(&gatt[(size_t)n * 256 + 2 * tt],     w * vf.x);
        atomicAdd(&gatt[(size_t)n * 256 + 2 * tt + 1], w * vf.y);
    }
}

__global__ void attn_finalize_kernel(const float* __restrict__ gatt, const float* __restrict__ expsum,
                                     const float* __restrict__ vsum, float invE,
                                     __half* __restrict__ out) {
    int n = blockIdx.x, t = threadIdx.x;
    float es = expsum[n * 4 + (t >> 6)];
    float val = (es > 0.f) ? gatt[(size_t)n * 256 + t] / es : vsum[t] * invE;
    out[(size_t)n * 256 + t] = __float2half_rn(val);
}

// ================= templated mma.sync GEMM =================
// C[M, 256*gy] = A[M,K]@B[Ncols,K]^T + bias (+resid); GN template arg enables fused
// GroupNorm(groups of 8)+ReLU epilogue. KC chunks of 64 K-elems. 3-stage cp.async.
// CTA tile 128x256, 8 warps (2x4), warp tile 64x64.
template <bool GN>
__global__ void __launch_bounds__(256) tc_gemm_kernel(
    const __half* __restrict__ A1, int KC,
    const __half* __restrict__ B1,
    const float* __restrict__ bias,
    const float* __restrict__ resid,
    float* __restrict__ Cf, int ldc,
    __half* __restrict__ Cb, int bld, int bofs,
    const float* __restrict__ gng, const float* __restrict__ gnb,
    int M)
{
    extern __shared__ char smem_raw[];
    char* smem = (char*)(((uintptr_t)smem_raw + 1023) & ~(uintptr_t)1023);
    uint32_t sbase = smem_to_u32(smem);

    int tid = threadIdx.x;
    int wid = tid >> 5;
    int lane = tid & 31;
    int g = lane >> 2, tg = lane & 3;
    int wm = (wid >> 2) * 64;
    int wn = (wid & 3) * 64;

    int rowBase = blockIdx.x * 128;
    int colBase = blockIdx.y * 256;

    int ar = tid >> 1;
    int au = (tid & 1) * 4;
    bool avalid = (rowBase + ar) < M;
    const char* Arow = (const char*)(A1 + (size_t)(rowBase + ar) * (KC * 64));
    const char* Brow = (const char*)(B1 + (size_t)(colBase + tid) * (KC * 64));

    auto load_chunk = [&](int c, int st) {
        uint32_t pA = sbase + st * 16384;
        uint32_t pB = sbase + 49152 + st * 32768;
        #pragma unroll
        for (int j = 0; j < 4; j++)
            cp_async16(pA + SMEM_SWIZZLE_128B(ar * 128 + (au + j) * 16),
                       Arow + (size_t)c * 128 + (au + j) * 16, avalid);
        #pragma unroll
        for (int j = 0; j < 8; j++)
            cp_async16(pB + SMEM_SWIZZLE_128B(tid * 128 + j * 16),
                       Brow + (size_t)c * 128 + j * 16, true);
    };

    float acc[4][8][4];
    #pragma unroll
    for (int mt = 0; mt < 4; mt++)
        #pragma unroll
        for (int nt = 0; nt < 8; nt++)
            #pragma unroll
            for (int i = 0; i < 4; i++) acc[mt][nt][i] = 0.f;

    load_chunk(0, 0); cp_commit();
    if (KC > 1) { load_chunk(1, 1); }
    cp_commit();

    uint32_t l15 = (uint32_t)(lane & 15);
    uint32_t lx  = (uint32_t)((lane & 7) << 4);
    uint32_t hi  = (uint32_t)(lane & 16);
    uint32_t aRowOff = (uint32_t)(wm + l15) * 128;
    uint32_t bRowOff = (uint32_t)(wn + l15) * 128;

    int st = 0;
    for (int c = 0; c < KC; c++) {
        cp_wait<1>();
        __syncthreads();
        if (c + 2 < KC) {
            int nst = st + 2; if (nst >= 3) nst -= 3;
            load_chunk(c + 2, nst);
        }
        cp_commit();

        uint32_t aB = sbase + st * 16384 + aRowOff;
        uint32_t bB = sbase + 49152 + st * 32768 + bRowOff;
        #pragma unroll
        for (int ks = 0; ks < 4; ks++) {
            uint32_t colp = ((uint32_t)(ks * 32) + hi) ^ lx;
            uint32_t a[4][4];
            #pragma unroll
            for (int mt = 0; mt < 4; mt++)
                ldsm4(a[mt][0], a[mt][1], a[mt][2], a[mt][3], aB + mt * 2048 + colp);
            #pragma unroll
            for (int ntp = 0; ntp < 4; ntp++) {
                uint32_t b0e, b0o, b1e, b1o;
                ldsm4(b0e, b0o, b1e, b1o, bB + ntp * 2048 + colp);
                #pragma unroll
                for (int mt = 0; mt < 4; mt++) {
                    mma16816(acc[mt][2 * ntp],     a[mt], b0e, b1e);
                    mma16816(acc[mt][2 * ntp + 1], a[mt], b0o, b1o);
                }
            }
        }
        st++; if (st >= 3) st = 0;
    }

    // ---- epilogue ----
    #pragma unroll
    for (int mt = 0; mt < 4; mt++) {
        #pragma unroll
        for (int half = 0; half < 2; half++) {
            int row = rowBase + wm + mt * 16 + g + half * 8;
            bool rv = row < M;
            #pragma unroll
            for (int nt = 0; nt < 8; nt++) {
                int col = wn + nt * 8 + tg * 2;
                int gcol = colBase + col;
                float v0 = acc[mt][nt][half * 2 + 0];
                float v1 = acc[mt][nt][half * 2 + 1];
                float2 bv = *(const float2*)(bias + gcol);
                v0 += bv.x; v1 += bv.y;
                if (resid && rv) {
                    float2 rvv = *(const float2*)(resid + (size_t)row * 256 + gcol);
                    v0 += rvv.x; v1 += rvv.y;
                }
                if (GN) {
                    float s = v0 + v1;
                    float s2 = v0 * v0 + v1 * v1;
                    s  += __shfl_xor_sync(0xffffffffu, s, 1);
                    s  += __shfl_xor_sync(0xffffffffu, s, 2);
                    s2 += __shfl_xor_sync(0xffffffffu, s2, 1);
                    s2 += __shfl_xor_sync(0xffffffffu, s2, 2);
                    float m = s * 0.125f;
                    float var = s2 * 0.125f - m * m;
                    float rs = rsqrtf(var + 1e-5f);
                    float2 gg = *(const float2*)(gng + gcol);
                    float2 bb = *(const float2*)(gnb + gcol);
                    v0 = fmaxf((v0 - m) * rs * gg.x + bb.x, 0.f);
                    v1 = fmaxf((v1 - m) * rs * gg.y + bb.y, 0.f);
                }
                if (rv) {
                    if (Cf)
                        *(float2*)(Cf + (size_t)row * ldc + gcol) = make_float2(v0, v1);
                    if (Cb) {
                        __half* o = Cb + (size_t)row * bld + bofs + gcol;
                        *(__half2*)(o) = __halves2half2(__float2half_rn(v0), __float2half_rn(v1));
                    }
                }
            }
        }
    }
}

// ================= launch =================
extern "C" void kernel_launch(void* const* d_in, const int* in_sizes, int n_in,
                              void* d_out, int out_size) {
    const float* x       = (const float*)d_in[0];
    const int*   ei      = (const int*)d_in[1];
    const float* ea      = (const float*)d_in[2];
    const float* gn_e1_g = (const float*)d_in[3];
    const float* gn_e1_b = (const float*)d_in[4];
    const float* We1     = (const float*)d_in[5];
    const float* be1     = (const float*)d_in[6];
    const float* gn_e2_g = (const float*)d_in[7];
    const float* gn_e2_b = (const float*)d_in[8];
    const float* We2     = (const float*)d_in[9];
    const float* be2     = (const float*)d_in[10];
    const float* gn_n_g  = (const float*)d_in[11];
    const float* gn_n_b  = (const float*)d_in[12];
    const float* Wq      = (const float*)d_in[13];
    const float* bq      = (const float*)d_in[14];
    const float* Wk      = (const float*)d_in[15];
    const float* bk      = (const float*)d_in[16];
    const float* Wv      = (const float*)d_in[17];
    const float* bv      = (const float*)d_in[18];
    const float* Wo      = (const float*)d_in[19];
    const float* bo      = (const float*)d_in[20];
    const float* Wn1     = (const float*)d_in[21];
    const float* bn1     = (const float*)d_in[22];
    const float* gn_n2_g = (const float*)d_in[23];
    const float* gn_n2_b = (const float*)d_in[24];
    const float* Wn2     = (const float*)d_in[25];
    const float* bn2     = (const float*)d_in[26];

    const int N = in_sizes[0] / 256;
    const int E = in_sizes[2] / 256;

    __half *ein, *h1b, *eoutb, *xb, *qh, *kvh, *gattb, *cat, *h2b;
    __half *We1t, *We2t, *Wqt, *Wkvt, *Wot, *Wn1t, *Wn2t;
    float *attbuf, *bkv;
    cudaGetSymbolAddress((void**)&ein,    g_ein);
    cudaGetSymbolAddress((void**)&h1b,    g_h1b);
    cudaGetSymbolAddress((void**)&eoutb,  g_eoutb);
    cudaGetSymbolAddress((void**)&xb,     g_xb);
    cudaGetSymbolAddress((void**)&qh,     g_qh);
    cudaGetSymbolAddress((void**)&kvh,    g_kvh);
    cudaGetSymbolAddress((void**)&attbuf, g_attbuf);
    cudaGetSymbolAddress((void**)&gattb,  g_gattb);
    cudaGetSymbolAddress((void**)&cat,    g_cat);
    cudaGetSymbolAddress((void**)&h2b,    g_h2b);
    cudaGetSymbolAddress((void**)&bkv,    g_bkv);
    cudaGetSymbolAddress((void**)&We1t,   g_We1t);
    cudaGetSymbolAddress((void**)&We2t,   g_We2t);
    cudaGetSymbolAddress((void**)&Wqt,    g_Wqt);
    cudaGetSymbolAddress((void**)&Wkvt,   g_Wkvt);
    cudaGetSymbolAddress((void**)&Wot,    g_Wot);
    cudaGetSymbolAddress((void**)&Wn1t,   g_Wn1t);
    cudaGetSymbolAddress((void**)&Wn2t,   g_Wn2t);

    float* n_out = (float*)d_out;
    float* e_out = (float*)d_out + (size_t)N * 256;
    float* gatt   = attbuf;
    float* expsum = attbuf + (size_t)N * 256;
    float* vsum   = expsum + (size_t)N * 4;

    const int DSMEM = 147456 + 1024;
    cudaFuncSetAttribute(tc_gemm_kernel<false>, cudaFuncAttributeMaxDynamicSharedMemorySize, DSMEM);
    cudaFuncSetAttribute(tc_gemm_kernel<true>,  cudaFuncAttributeMaxDynamicSharedMemorySize, DSMEM);

    int gemmE = (E + 127) / 128;
    int gemmN = (N + 127) / 128;

    WPA wpa;
    wpa.W[0] = We1; wpa.O[0] = We1t;           wpa.K[0] = 768;
    wpa.W[1] = We2; wpa.O[1] = We2t;           wpa.K[1] = 256;
    wpa.W[2] = Wq;  wpa.O[2] = Wqt;            wpa.K[2] = 256;
    wpa.W[3] = Wk;  wpa.O[3] = Wkvt;           wpa.K[3] = 256;
    wpa.W[4] = Wv;  wpa.O[4] = Wkvt + 256*256; wpa.K[4] = 256;
    wpa.W[5] = Wo;  wpa.O[5] = Wot;            wpa.K[5] = 256;
    wpa.W[6] = Wn1; wpa.O[6] = Wn1t;           wpa.K[6] = 512;
    wpa.W[7] = Wn2; wpa.O[7] = Wn2t;           wpa.K[7] = 256;
    int acc0 = 0;
    for (int i = 0; i < 8; i++) { wpa.start[i] = acc0; acc0 += wpa.K[i]; }
    wpa.start[8] = acc0;
    wprep_all_kernel<<<acc0, 256>>>(wpa);

    int zcount = N * 256 + N * 4 + 256;
    int miscTot = N * 256 + zcount + 512;
    misc_prep_kernel<<<(miscTot + 255) / 256, 256>>>(x, xb, attbuf, zcount, bk, bv, bkv, N);

    gn_edge_kernel<<<E, 256>>>(x, ei, ea, gn_e1_g, gn_e1_b, ein, E);

    // h1b = GN(ein @ We1 + be1)+ReLU fused, fp16 only
    tc_gemm_kernel<true><<<dim3(gemmE, 1), 256, DSMEM>>>(ein, 12, We1t, be1, nullptr,
                                                         nullptr, 0, h1b, 256, 0,
                                                         gn_e2_g, gn_e2_b, E);
    // e_out = h1b @ We2 + be2 + ea  [PROFILED LAUNCH index 5]
    tc_gemm_kernel<false><<<dim3(gemmE, 1), 256, DSMEM>>>(h1b, 4, We2t, be2, ea,
                                                          e_out, 256, eoutb, 256, 0,
                                                          nullptr, nullptr, E);
    // q = xb @ Wq + bq (fp16)
    tc_gemm_kernel<false><<<dim3(gemmN, 1), 256, DSMEM>>>(xb, 4, Wqt, bq, nullptr,
                                                          nullptr, 0, qh, 256, 0,
                                                          nullptr, nullptr, N);
    // kv = eoutb @ [Wk|Wv] (col-tiled, fp16)
    tc_gemm_kernel<false><<<dim3(gemmE, 2), 256, DSMEM>>>(eoutb, 4, Wkvt, bkv, nullptr,
                                                          nullptr, 0, kvh, 512, 0,
                                                          nullptr, nullptr, E);
    colsum_kernel<<<64, 256>>>(kvh, vsum, E);
    attn_scatter2_kernel<<<(E + 1) / 2, 256>>>(qh, kvh, ei, expsum, gatt, E);
    attn_finalize_kernel<<<N, 256>>>(gatt, expsum, vsum, 1.0f / (float)E, gattb);
    // g_o = gattb @ Wo + bo -> cat right half (fp16)
    tc_gemm_kernel<false><<<dim3(gemmN, 1), 256, DSMEM>>>(gattb, 4, Wot, bo, nullptr,
                                                          nullptr, 0, cat, 512, 256,
                                                          nullptr, nullptr, N);
    // xa = GN(x)+ReLU -> cat left half
    gn256b_kernel<<<(N + 7) / 8, 256>>>(x, gn_n_g, gn_n_b, cat, 512, 0, N);
    // h2b = GN(cat @ Wn1 + bn1)+ReLU fused, fp16 only
    tc_gemm_kernel<true><<<dim3(gemmN, 1), 256, DSMEM>>>(cat, 8, Wn1t, bn1, nullptr,
                                                         nullptr, 0, h2b, 256, 0,
                                                         gn_n2_g, gn_n2_b, N);
    // n_out = h2b @ Wn2 + bn2 + x
    tc_gemm_kernel<false><<<dim3(gemmN, 1), 256, DSMEM>>>(h2b, 4, Wn2t, bn2, x,
                                                          n_out, 256, nullptr, 0, 0,
                                                          nullptr, nullptr, N);
}

// round 16
// speedup vs baseline: 1.3307x; 1.2583x over previous
#include <cuda_runtime.h>
#include <cuda_fp16.h>
#include <cstdint>
#include <cstddef>

// ================= problem constants =================
#define MAX_E 16000
#define MAX_N 2000

// ================= helpers =================
__device__ __forceinline__ uint32_t smem_to_u32(const void* smem_ptr) {
    uint32_t addr;
    asm("{ .reg .u64 tmp; cvta.to.shared.u64 tmp, %1; cvt.u32.u64 %0, tmp; }"
        : "=r"(addr) : "l"(smem_ptr));
    return addr;
}
#define SMEM_SWIZZLE_128B(byte_offset) ((byte_offset) ^ (((byte_offset) >> 3) & 0x70))

__device__ __forceinline__ void cp_async16(uint32_t dst, const void* src, bool valid) {
    int sz = valid ? 16 : 0;
    asm volatile("cp.async.cg.shared.global [%0], [%1], 16, %2;"
                 :: "r"(dst), "l"(src), "r"(sz) : "memory");
}
__device__ __forceinline__ void cp_commit() {
    asm volatile("cp.async.commit_group;" ::: "memory");
}
template <int N>
__device__ __forceinline__ void cp_wait() {
    asm volatile("cp.async.wait_group %0;" :: "n"(N) : "memory");
}
__device__ __forceinline__ void ldsm4(uint32_t& r0, uint32_t& r1, uint32_t& r2, uint32_t& r3,
                                      uint32_t addr) {
    asm volatile("ldmatrix.sync.aligned.m8n8.x4.shared.b16 {%0,%1,%2,%3}, [%4];"
                 : "=r"(r0), "=r"(r1), "=r"(r2), "=r"(r3) : "r"(addr));
}
__device__ __forceinline__ void mma16816(float* c, const uint32_t* a, uint32_t b0, uint32_t b1) {
    asm volatile(
        "mma.sync.aligned.m16n8k16.row.col.f32.f16.f16.f32 "
        "{%0,%1,%2,%3}, {%4,%5,%6,%7}, {%8,%9}, {%0,%1,%2,%3};"
        : "+f"(c[0]), "+f"(c[1]), "+f"(c[2]), "+f"(c[3])
        : "r"(a[0]), "r"(a[1]), "r"(a[2]), "r"(a[3]), "r"(b0), "r"(b1));
}

// ================= scratch =================
__device__ __align__(256) __half g_ein[(size_t)MAX_E * 768];
__device__ __align__(256) __half g_h1b[(size_t)MAX_E * 256];
__device__ __align__(256) __half g_eoutb[(size_t)MAX_E * 256];
__device__ __align__(256) __half g_xb[(size_t)MAX_N * 256];
__device__ __align__(256) __half g_qh[(size_t)MAX_N * 256];
__device__ __align__(256) __half g_kvh[(size_t)MAX_E * 512];
__device__ __align__(256) float  g_attbuf[(size_t)MAX_N * 256 + MAX_N * 4 + 256];
__device__ __align__(256) __half g_gattb[(size_t)MAX_N * 256];
__device__ __align__(256) __half g_cat[(size_t)MAX_N * 512];
__device__ __align__(256) __half g_h2b[(size_t)MAX_N * 256];
__device__ __align__(256) float  g_bkv[512];
// single-term fp16 transposed weights [Ncols, K]
__device__ __align__(256) __half g_We1t[256 * 768];
__device__ __align__(256) __half g_We2t[256 * 256];
__device__ __align__(256) __half g_Wqt[256 * 256];
__device__ __align__(256) __half g_Wkvt[512 * 256];
__device__ __align__(256) __half g_Wot[256 * 256];
__device__ __align__(256) __half g_Wn1t[256 * 512];
__device__ __align__(256) __half g_Wn2t[256 * 256];

// ================= fused prep =================
struct WPA {
    const float* W[8];
    __half* O[8];
    int K[8];
    int start[9];
};
__global__ void wprep_all_kernel(WPA a) {
    int b = blockIdx.x;
    int i = 0;
    #pragma unroll
    for (int j = 1; j < 8; j++) if (b >= a.start[j]) i = j;
    int k = b - a.start[i];
    int K = a.K[i];
    int col = threadIdx.x;
    a.O[i][(size_t)col * K + k] = __float2half_rn(a.W[i][(size_t)k * 256 + col]);
}

__global__ void misc_prep_kernel(const float* __restrict__ x, __half* __restrict__ xb,
                                 float* __restrict__ attbuf, int zcount,
                                 const float* __restrict__ bk, const float* __restrict__ bv,
                                 float* __restrict__ bkv, int M) {
    int idx = blockIdx.x * blockDim.x + threadIdx.x;
    if (idx < M * 256)
        xb[idx] = __float2half_rn(x[idx]);
    int z = idx - M * 256;
    if (z >= 0 && z < zcount) attbuf[z] = 0.f;
    int bidx = idx - M * 256 - zcount;
    if (bidx >= 0 && bidx < 512)
        bkv[bidx] = (bidx < 256) ? bk[bidx] : bv[bidx - 256];
}

// GN(768, 32 groups of 24)+ReLU over concat(x[row],x[col],ea) -> fp16 [E,768]
__global__ void gn_edge_kernel(const float* __restrict__ x, const int* __restrict__ ei,
                               const float* __restrict__ ea,
                               const float* __restrict__ gamma, const float* __restrict__ beta,
                               __half* __restrict__ out, int E) {
    __shared__ float buf[768];
    __shared__ float s_mu[32], s_rs[32];
    int e = blockIdx.x;
    int t = threadIdx.x;
    int r = ei[e];
    int c = ei[E + e];
    buf[t]       = x[(size_t)r * 256 + t];
    buf[256 + t] = x[(size_t)c * 256 + t];
    buf[512 + t] = ea[(size_t)e * 256 + t];
    __syncthreads();
    if (t < 32) {
        float s = 0.f, s2 = 0.f;
        #pragma unroll
        for (int i = 0; i < 24; i++) { float v = buf[t * 24 + i]; s += v; s2 += v * v; }
        float m = s * (1.f / 24.f);
        float var = s2 * (1.f / 24.f) - m * m;
        s_mu[t] = m; s_rs[t] = rsqrtf(var + 1e-5f);
    }
    __syncthreads();
    size_t base = (size_t)e * 768;
    #pragma unroll
    for (int i = t; i < 768; i += 256) {
        int grp = i / 24;
        float v = fmaxf((buf[i] - s_mu[grp]) * s_rs[grp] * gamma[i] + beta[i], 0.f);
        out[base + i] = __float2half_rn(v);
    }
}

// scatter (2 edges/block, half2) + colsum tail blocks
__global__ void attn_scatter2_kernel(const __half* __restrict__ q, const __half* __restrict__ kv,
                                     const int* __restrict__ ei,
                                     float* __restrict__ expsum, float* __restrict__ gatt,
                                     float* __restrict__ vsum, int sblocks, int E) {
    int t = threadIdx.x;
    if ((int)blockIdx.x >= sblocks) {
        // colsum duty: 64 tail blocks, stride-64 over edges
        float s = 0.f;
        for (int e = blockIdx.x - sblocks; e < E; e += 64)
            s += __half2float(kv[(size_t)e * 512 + 256 + t]);
        atomicAdd(&vsum[t], s);
        return;
    }
    __shared__ float wsum[8];
    __shared__ float wexp[2][4];
    int sub = t >> 7;
    int tt = t & 127;
    int e = blockIdx.x * 2 + sub;
    bool ev = e < E;
    int n = 0;
    float p = 0.f;
    float2 vf = make_float2(0.f, 0.f);
    if (ev) {
        n = ei[E + e];
        __half2 qv = *(const __half2*)(q + (size_t)n * 256 + 2 * tt);
        __half2 kvv = *(const __half2*)(kv + (size_t)e * 512 + 2 * tt);
        __half2 vv = *(const __half2*)(kv + (size_t)e * 512 + 256 + 2 * tt);
        float2 qf = __half22float2(qv);
        float2 kf = __half22float2(kvv);
        vf = __half22float2(vv);
        p = qf.x * kf.x + qf.y * kf.y;
    }
    #pragma unroll
    for (int off = 16; off >= 1; off >>= 1)
        p += __shfl_xor_sync(0xffffffffu, p, off);
    int warp = t >> 5, lane = t & 31;
    if (lane == 0) wsum[warp] = p;
    __syncthreads();
    if (t < 8) {
        int s = t >> 2, h = t & 3;
        float w = expf(wsum[t] * 0.125f);
        wexp[s][h] = w;
        int ee = blockIdx.x * 2 + s;
        if (ee < E)
            atomicAdd(&expsum[ei[E + ee] * 4 + h], w);
    }
    __syncthreads();
    if (ev) {
        float w = wexp[sub][tt >> 5];
        atomicAdd(&gatt[(size_t)n * 256 + 2 * tt],     w * vf.x);
        atomicAdd(&gatt[(size_t)n * 256 + 2 * tt + 1], w * vf.y);
    }
}

// merged: blocks [0,N) attention finalize -> gattb; blocks [N, N+ceil(N/8)) GN(x)->cat left
__global__ void attn_post_kernel(const float* __restrict__ gatt, const float* __restrict__ expsum,
                                 const float* __restrict__ vsum, float invE,
                                 __half* __restrict__ gattb,
                                 const float* __restrict__ x,
                                 const float* __restrict__ gng, const float* __restrict__ gnb,
                                 __half* __restrict__ cat, int N) {
    int t = threadIdx.x;
    if ((int)blockIdx.x < N) {
        int n = blockIdx.x;
        float es = expsum[n * 4 + (t >> 6)];
        float val = (es > 0.f) ? gatt[(size_t)n * 256 + t] / es : vsum[t] * invE;
        gattb[(size_t)n * 256 + t] = __float2half_rn(val);
        return;
    }
    int row = (blockIdx.x - N) * 8 + (t >> 5);
    if (row >= N) return;
    int g = t & 31;
    const float* p = x + (size_t)row * 256 + g * 8;
    float4 a = *(const float4*)p;
    float4 b = *(const float4*)(p + 4);
    float s = a.x + a.y + a.z + a.w + b.x + b.y + b.z + b.w;
    float s2 = a.x*a.x + a.y*a.y + a.z*a.z + a.w*a.w + b.x*b.x + b.y*b.y + b.z*b.z + b.w*b.w;
    float m = s * 0.125f;
    float var = s2 * 0.125f - m * m;
    float rs = rsqrtf(var + 1e-5f);
    float vals[8] = {a.x, a.y, a.z, a.w, b.x, b.y, b.z, b.w};
    __half hs[8];
    #pragma unroll
    for (int i = 0; i < 8; i++) {
        int ch = g * 8 + i;
        hs[i] = __float2half_rn(fmaxf((vals[i] - m) * rs * gng[ch] + gnb[ch], 0.f));
    }
    __half* o = cat + (size_t)row * 512 + g * 8;
    #pragma unroll
    for (int i = 0; i < 4; i++)
        *(__half2*)(o + 2*i) = __halves2half2(hs[2*i], hs[2*i+1]);
}

// GN(256, groups of 8)+ReLU over fp32 input -> fp16 out (used post-Wn1? no — kept for h2b path no; unused)
// (removed)

// ================= templated mma.sync GEMM =================
// C[M, 256*gy] = A[M,K]@B[Ncols,K]^T + bias (+resid); GN template arg enables fused
// GroupNorm(groups of 8)+ReLU epilogue. KC chunks of 64 K-elems. 3-stage cp.async.
// CTA tile 128x256, 8 warps (2x4), warp tile 64x64.
template <bool GN>
__global__ void __launch_bounds__(256) tc_gemm_kernel(
    const __half* __restrict__ A1, int KC,
    const __half* __restrict__ B1,
    const float* __restrict__ bias,
    const float* __restrict__ resid,
    float* __restrict__ Cf, int ldc,
    __half* __restrict__ Cb, int bld, int bofs,
    const float* __restrict__ gng, const float* __restrict__ gnb,
    int M)
{
    extern __shared__ char smem_raw[];
    char* smem = (char*)(((uintptr_t)smem_raw + 1023) & ~(uintptr_t)1023);
    uint32_t sbase = smem_to_u32(smem);

    int tid = threadIdx.x;
    int wid = tid >> 5;
    int lane = tid & 31;
    int g = lane >> 2, tg = lane & 3;
    int wm = (wid >> 2) * 64;
    int wn = (wid & 3) * 64;

    int rowBase = blockIdx.x * 128;
    int colBase = blockIdx.y * 256;

    int ar = tid >> 1;
    int au = (tid & 1) * 4;
    bool avalid = (rowBase + ar) < M;
    const char* Arow = (const char*)(A1 + (size_t)(rowBase + ar) * (KC * 64));
    const char* Brow = (const char*)(B1 + (size_t)(colBase + tid) * (KC * 64));

    auto load_chunk = [&](int c, int st) {
        uint32_t pA = sbase + st * 16384;
        uint32_t pB = sbase + 49152 + st * 32768;
        #pragma unroll
        for (int j = 0; j < 4; j++)
            cp_async16(pA + SMEM_SWIZZLE_128B(ar * 128 + (au + j) * 16),
                       Arow + (size_t)c * 128 + (au + j) * 16, avalid);
        #pragma unroll
        for (int j = 0; j < 8; j++)
            cp_async16(pB + SMEM_SWIZZLE_128B(tid * 128 + j * 16),
                       Brow + (size_t)c * 128 + j * 16, true);
    };

    float acc[4][8][4];
    #pragma unroll
    for (int mt = 0; mt < 4; mt++)
        #pragma unroll
        for (int nt = 0; nt < 8; nt++)
            #pragma unroll
            for (int i = 0; i < 4; i++) acc[mt][nt][i] = 0.f;

    load_chunk(0, 0); cp_commit();
    if (KC > 1) { load_chunk(1, 1); }
    cp_commit();

    uint32_t l15 = (uint32_t)(lane & 15);
    uint32_t lx  = (uint32_t)((lane & 7) << 4);
    uint32_t hi  = (uint32_t)(lane & 16);
    uint32_t aRowOff = (uint32_t)(wm + l15) * 128;
    uint32_t bRowOff = (uint32_t)(wn + l15) * 128;

    int st = 0;
    for (int c = 0; c < KC; c++) {
        cp_wait<1>();
        __syncthreads();
        if (c + 2 < KC) {
            int nst = st + 2; if (nst >= 3) nst -= 3;
            load_chunk(c + 2, nst);
        }
        cp_commit();

        uint32_t aB = sbase + st * 16384 + aRowOff;
        uint32_t bB = sbase + 49152 + st * 32768 + bRowOff;
        #pragma unroll
        for (int ks = 0; ks < 4; ks++) {
            uint32_t colp = ((uint32_t)(ks * 32) + hi) ^ lx;
            uint32_t a[4][4];
            #pragma unroll
            for (int mt = 0; mt < 4; mt++)
                ldsm4(a[mt][0], a[mt][1], a[mt][2], a[mt][3], aB + mt * 2048 + colp);
            #pragma unroll
            for (int ntp = 0; ntp < 4; ntp++) {
                uint32_t b0e, b0o, b1e, b1o;
                ldsm4(b0e, b0o, b1e, b1o, bB + ntp * 2048 + colp);
                #pragma unroll
                for (int mt = 0; mt < 4; mt++) {
                    mma16816(acc[mt][2 * ntp],     a[mt], b0e, b1e);
                    mma16816(acc[mt][2 * ntp + 1], a[mt], b0o, b1o);
                }
            }
        }
        st++; if (st >= 3) st = 0;
    }

    // ---- epilogue ----
    #pragma unroll
    for (int mt = 0; mt < 4; mt++) {
        #pragma unroll
        for (int half = 0; half < 2; half++) {
            int row = rowBase + wm + mt * 16 + g + half * 8;
            bool rv = row < M;
            #pragma unroll
            for (int nt = 0; nt < 8; nt++) {
                int col = wn + nt * 8 + tg * 2;
                int gcol = colBase + col;
                float v0 = acc[mt][nt][half * 2 + 0];
                float v1 = acc[mt][nt][half * 2 + 1];
                float2 bv = *(const float2*)(bias + gcol);
                v0 += bv.x; v1 += bv.y;
                if (resid && rv) {
                    float2 rvv = *(const float2*)(resid + (size_t)row * 256 + gcol);
                    v0 += rvv.x; v1 += rvv.y;
                }
                if (GN) {
                    float s = v0 + v1;
                    float s2 = v0 * v0 + v1 * v1;
                    s  += __shfl_xor_sync(0xffffffffu, s, 1);
                    s  += __shfl_xor_sync(0xffffffffu, s, 2);
                    s2 += __shfl_xor_sync(0xffffffffu, s2, 1);
                    s2 += __shfl_xor_sync(0xffffffffu, s2, 2);
                    float m = s * 0.125f;
                    float var = s2 * 0.125f - m * m;
                    float rs = rsqrtf(var + 1e-5f);
                    float2 gg = *(const float2*)(gng + gcol);
                    float2 bb = *(const float2*)(gnb + gcol);
                    v0 = fmaxf((v0 - m) * rs * gg.x + bb.x, 0.f);
                    v1 = fmaxf((v1 - m) * rs * gg.y + bb.y, 0.f);
                }
                if (rv) {
                    if (Cf)
                        *(float2*)(Cf + (size_t)row * ldc + gcol) = make_float2(v0, v1);
                    if (Cb) {
                        __half* o = Cb + (size_t)row * bld + bofs + gcol;
                        *(__half2*)(o) = __halves2half2(__float2half_rn(v0), __float2half_rn(v1));
                    }
                }
            }
        }
    }
}

// ================= launch =================
extern "C" void kernel_launch(void* const* d_in, const int* in_sizes, int n_in,
                              void* d_out, int out_size) {
    const float* x       = (const float*)d_in[0];
    const int*   ei      = (const int*)d_in[1];
    const float* ea      = (const float*)d_in[2];
    const float* gn_e1_g = (const float*)d_in[3];
    const float* gn_e1_b = (const float*)d_in[4];
    const float* We1     = (const float*)d_in[5];
    const float* be1     = (const float*)d_in[6];
    const float* gn_e2_g = (const float*)d_in[7];
    const float* gn_e2_b = (const float*)d_in[8];
    const float* We2     = (const float*)d_in[9];
    const float* be2     = (const float*)d_in[10];
    const float* gn_n_g  = (const float*)d_in[11];
    const float* gn_n_b  = (const float*)d_in[12];
    const float* Wq      = (const float*)d_in[13];
    const float* bq      = (const float*)d_in[14];
    const float* Wk      = (const float*)d_in[15];
    const float* bk      = (const float*)d_in[16];
    const float* Wv      = (const float*)d_in[17];
    const float* bv      = (const float*)d_in[18];
    const float* Wo      = (const float*)d_in[19];
    const float* bo      = (const float*)d_in[20];
    const float* Wn1     = (const float*)d_in[21];
    const float* bn1     = (const float*)d_in[22];
    const float* gn_n2_g = (const float*)d_in[23];
    const float* gn_n2_b = (const float*)d_in[24];
    const float* Wn2     = (const float*)d_in[25];
    const float* bn2     = (const float*)d_in[26];

    const int N = in_sizes[0] / 256;
    const int E = in_sizes[2] / 256;

    __half *ein, *h1b, *eoutb, *xb, *qh, *kvh, *gattb, *cat, *h2b;
    __half *We1t, *We2t, *Wqt, *Wkvt, *Wot, *Wn1t, *Wn2t;
    float *attbuf, *bkv;
    cudaGetSymbolAddress((void**)&ein,    g_ein);
    cudaGetSymbolAddress((void**)&h1b,    g_h1b);
    cudaGetSymbolAddress((void**)&eoutb,  g_eoutb);
    cudaGetSymbolAddress((void**)&xb,     g_xb);
    cudaGetSymbolAddress((void**)&qh,     g_qh);
    cudaGetSymbolAddress((void**)&kvh,    g_kvh);
    cudaGetSymbolAddress((void**)&attbuf, g_attbuf);
    cudaGetSymbolAddress((void**)&gattb,  g_gattb);
    cudaGetSymbolAddress((void**)&cat,    g_cat);
    cudaGetSymbolAddress((void**)&h2b,    g_h2b);
    cudaGetSymbolAddress((void**)&bkv,    g_bkv);
    cudaGetSymbolAddress((void**)&We1t,   g_We1t);
    cudaGetSymbolAddress((void**)&We2t,   g_We2t);
    cudaGetSymbolAddress((void**)&Wqt,    g_Wqt);
    cudaGetSymbolAddress((void**)&Wkvt,   g_Wkvt);
    cudaGetSymbolAddress((void**)&Wot,    g_Wot);
    cudaGetSymbolAddress((void**)&Wn1t,   g_Wn1t);
    cudaGetSymbolAddress((void**)&Wn2t,   g_Wn2t);

    float* n_out = (float*)d_out;
    float* e_out = (float*)d_out + (size_t)N * 256;
    float* gatt   = attbuf;
    float* expsum = attbuf + (size_t)N * 256;
    float* vsum   = expsum + (size_t)N * 4;

    const int DSMEM = 147456 + 1024;
    cudaFuncSetAttribute(tc_gemm_kernel<false>, cudaFuncAttributeMaxDynamicSharedMemorySize, DSMEM);
    cudaFuncSetAttribute(tc_gemm_kernel<true>,  cudaFuncAttributeMaxDynamicSharedMemorySize, DSMEM);

    int gemmE = (E + 127) / 128;
    int gemmN = (N + 127) / 128;

    WPA wpa;
    wpa.W[0] = We1; wpa.O[0] = We1t;           wpa.K[0] = 768;
    wpa.W[1] = We2; wpa.O[1] = We2t;           wpa.K[1] = 256;
    wpa.W[2] = Wq;  wpa.O[2] = Wqt;            wpa.K[2] = 256;
    wpa.W[3] = Wk;  wpa.O[3] = Wkvt;           wpa.K[3] = 256;
    wpa.W[4] = Wv;  wpa.O[4] = Wkvt + 256*256; wpa.K[4] = 256;
    wpa.W[5] = Wo;  wpa.O[5] = Wot;            wpa.K[5] = 256;
    wpa.W[6] = Wn1; wpa.O[6] = Wn1t;           wpa.K[6] = 512;
    wpa.W[7] = Wn2; wpa.O[7] = Wn2t;           wpa.K[7] = 256;
    int acc0 = 0;
    for (int i = 0; i < 8; i++) { wpa.start[i] = acc0; acc0 += wpa.K[i]; }
    wpa.start[8] = acc0;
    wprep_all_kernel<<<acc0, 256>>>(wpa);

    int zcount = N * 256 + N * 4 + 256;
    int miscTot = N * 256 + zcount + 512;
    misc_prep_kernel<<<(miscTot + 255) / 256, 256>>>(x, xb, attbuf, zcount, bk, bv, bkv, N);

    gn_edge_kernel<<<E, 256>>>(x, ei, ea, gn_e1_g, gn_e1_b, ein, E);

    // h1b = GN(ein @ We1 + be1)+ReLU fused, fp16 only
    tc_gemm_kernel<true><<<dim3(gemmE, 1), 256, DSMEM>>>(ein, 12, We1t, be1, nullptr,
                                                         nullptr, 0, h1b, 256, 0,
                                                         gn_e2_g, gn_e2_b, E);
    // e_out = h1b @ We2 + be2 + ea
    tc_gemm_kernel<false><<<dim3(gemmE, 1), 256, DSMEM>>>(h1b, 4, We2t, be2, ea,
                                                          e_out, 256, eoutb, 256, 0,
                                                          nullptr, nullptr, E);
    // q = xb @ Wq + bq (fp16)
    tc_gemm_kernel<false><<<dim3(gemmN, 1), 256, DSMEM>>>(xb, 4, Wqt, bq, nullptr,
                                                          nullptr, 0, qh, 256, 0,
                                                          nullptr, nullptr, N);
    // kv = eoutb @ [Wk|Wv] (col-tiled, fp16)
    tc_gemm_kernel<false><<<dim3(gemmE, 2), 256, DSMEM>>>(eoutb, 4, Wkvt, bkv, nullptr,
                                                          nullptr, 0, kvh, 512, 0,
                                                          nullptr, nullptr, E);
    // scatter + colsum in one launch
    int sblocks = (E + 1) / 2;
    attn_scatter2_kernel<<<sblocks + 64, 256>>>(qh, kvh, ei, expsum, gatt, vsum, sblocks, E);
    // finalize + GN(x)->cat left in one launch
    attn_post_kernel<<<N + (N + 7) / 8, 256>>>(gatt, expsum, vsum, 1.0f / (float)E,
                                               gattb, x, gn_n_g, gn_n_b, cat, N);
    // g_o = gattb @ Wo + bo -> cat right half (fp16)
    tc_gemm_kernel<false><<<dim3(gemmN, 1), 256, DSMEM>>>(gattb, 4, Wot, bo, nullptr,
                                                          nullptr, 0, cat, 512, 256,
                                                          nullptr, nullptr, N);
    // h2b = GN(cat @ Wn1 + bn1)+ReLU fused, fp16 only
    tc_gemm_kernel<true><<<dim3(gemmN, 1), 256, DSMEM>>>(cat, 8, Wn1t, bn1, nullptr,
                                                         nullptr, 0, h2b, 256, 0,
                                                         gn_n2_g, gn_n2_b, N);
    // n_out = h2b @ Wn2 + bn2 + x
    tc_gemm_kernel<false><<<dim3(gemmN, 1), 256, DSMEM>>>(h2b, 4, Wn2t, bn2, x,
                                                          n_out, 256, nullptr, 0, 0,
                                                          nullptr, nullptr, N);
}